// round 5
// baseline (speedup 1.0000x reference)
#include <cuda_runtime.h>
#include <cstdint>

#define BATCH  32
#define CIN    64
#define COUT   8
#define HW     65536
#define KSTEPS 11

// Scratch (static __device__ — allocation-free per harness rules)
__device__ float4 g_feat0[(size_t)BATCH * HW];           // 32 MB: channels 0-3
__device__ float4 g_feat1[(size_t)BATCH * HW];           // 32 MB: channels 4-7
__device__ unsigned long long g_slots[KSTEPS][BATCH];    // argmax slots per step

// -------------------------------------------------------------------------
__global__ void k_init_slots() {
    int t = threadIdx.x;
    if (t < KSTEPS * BATCH) ((unsigned long long*)g_slots)[t] = 0ull;
}

// Block-wide max of packed (value_bits<<32 | ~idx). Valid on thread 0.
__device__ __forceinline__ unsigned long long block_reduce_max(
        unsigned long long v, unsigned long long* sred) {
    #pragma unroll
    for (int s = 16; s > 0; s >>= 1) {
        unsigned long long o = __shfl_down_sync(0xFFFFFFFFu, v, s);
        if (o > v) v = o;
    }
    if ((threadIdx.x & 31) == 0) sred[threadIdx.x >> 5] = v;
    __syncthreads();
    if (threadIdx.x < 8) {
        v = sred[threadIdx.x];
        #pragma unroll
        for (int s = 4; s > 0; s >>= 1) {
            unsigned long long o = __shfl_down_sync(0x000000FFu, v, s);
            if (o > v) v = o;
        }
    }
    return v;
}

__device__ __forceinline__ unsigned long long pack_key(float key, int idx) {
    return ((unsigned long long)__float_as_uint(key) << 32)
         | (unsigned long long)(0xFFFFFFFFu - (unsigned)idx);
}

// Packed fp32x2 helpers (sm_103a packed-FMA pipe, rt=1 vs 2 for scalar FFMA)
__device__ __forceinline__ unsigned long long pack2(float lo, float hi) {
    unsigned long long r;
    asm("mov.b64 %0, {%1, %2};" : "=l"(r) : "f"(lo), "f"(hi));
    return r;
}
__device__ __forceinline__ void unpack2(float& lo, float& hi, unsigned long long v) {
    asm("mov.b64 {%0, %1}, %2;" : "=f"(lo), "=f"(hi) : "l"(v));
}
__device__ __forceinline__ void ffma2(unsigned long long& d,
                                      unsigned long long a, unsigned long long b) {
    asm("fma.rn.f32x2 %0, %1, %2, %0;" : "+l"(d) : "l"(a), "l"(b));
}

// -------------------------------------------------------------------------
// Kernel 0: feat = gate*(W@x + b) + coord grid; scopes[:,0]=1;
// partial argmax of rand into slot 0. Inner GEMM uses packed f32x2 FMA.
// Grid: 2048 blocks x 256 threads, 4 consecutive pixels/thread (x coalesced).
__global__ void __launch_bounds__(256) k_feat(
        const float* __restrict__ x, const float* __restrict__ rnd,
        const float* __restrict__ w, const float* __restrict__ bias,
        const float* __restrict__ gate_p, float* __restrict__ out) {
    __shared__ unsigned long long swp[CIN * COUT];   // duplicated packed weights [c][o]
    __shared__ float sb[COUT];
    __shared__ unsigned long long sred[8];
    int tid = threadIdx.x;
    for (int i = tid; i < CIN * COUT; i += 256) {
        int o = i / CIN, c = i % CIN;
        float wv = w[i];
        swp[c * COUT + o] = pack2(wv, wv);           // transposed + duplicated
    }
    if (tid < COUT) sb[tid] = bias[tid];
    __syncthreads();

    float gate = *gate_p;
    int b     = blockIdx.x >> 6;
    int pin   = (blockIdx.x & 63) * 1024 + tid * 4;   // pixel-in-batch
    const float4* x4 = (const float4*)x + ((size_t)b * CIN) * (HW / 4) + (pin >> 2);

    unsigned long long acc[COUT][2];                  // pairs: px{0,1}, px{2,3}
    #pragma unroll
    for (int o = 0; o < COUT; o++) {
        float bv = sb[o];
        acc[o][0] = pack2(bv, bv);
        acc[o][1] = pack2(bv, bv);
    }

    #pragma unroll 8
    for (int c = 0; c < CIN; c++) {
        float4 v = __ldcs(&x4[(size_t)c * (HW / 4)]);   // x never re-read: stream
        unsigned long long xp0 = pack2(v.x, v.y);
        unsigned long long xp1 = pack2(v.z, v.w);
        #pragma unroll
        for (int o = 0; o < COUT; o++) {
            unsigned long long wp = swp[c * COUT + o];
            ffma2(acc[o][0], wp, xp0);
            ffma2(acc[o][1], wp, xp1);
        }
    }

    float accf[COUT][4];
    #pragma unroll
    for (int o = 0; o < COUT; o++) {
        unpack2(accf[o][0], accf[o][1], acc[o][0]);
        unpack2(accf[o][2], accf[o][3], acc[o][1]);
    }

    const float step = 2.0f / 255.0f;
    #pragma unroll
    for (int j = 0; j < 4; j++) {
        int p  = pin + j;
        int h  = p >> 8;
        int wi = p & 255;
        float4 f0, f1;
        f0.x = gate * accf[0][j]; f0.y = gate * accf[1][j];
        f0.z = gate * accf[2][j]; f0.w = gate * accf[3][j];
        f1.x = gate * accf[4][j]; f1.y = gate * accf[5][j];
        f1.z = fmaf((float)h,  step, -1.0f) + gate * accf[6][j];
        f1.w = fmaf((float)wi, step, -1.0f) + gate * accf[7][j];
        size_t fb = (size_t)b * HW + p;
        __stcs(&g_feat0[fb], f0);            // streamed: re-read via __ldcs later
        __stcs(&g_feat1[fb], f1);
    }

    // scopes[b,0,:] = 1  (re-read by step 0 -> normal store, stays in L2)
    float4 ones = make_float4(1.0f, 1.0f, 1.0f, 1.0f);
    float* scopes = out + (size_t)BATCH * KSTEPS * HW;
    *(float4*)&scopes[((size_t)b * KSTEPS) * HW + pin] = ones;

    // argmax of rand (scope == 1) for step 0
    float4 rv = ((const float4*)rnd)[((size_t)b * HW + pin) >> 2];
    float rj[4] = {rv.x, rv.y, rv.z, rv.w};
    unsigned long long best = 0ull;
    #pragma unroll
    for (int j = 0; j < 4; j++) {
        unsigned long long pk = pack_key(rj[j], pin + j);
        if (pk > best) best = pk;
    }
    best = block_reduce_max(best, sred);
    if (tid == 0) atomicMax(&g_slots[0][b], best);
}

// -------------------------------------------------------------------------
// Step kernel k = 0..9: seed from slot[k]; alpha; write masks[:,k],
// scopes[:,k+1]; partial argmax into slot[k+1] (k==9 -> masks[:,10]=scope).
// Policy: STREAM the big feat set (__ldcs), keep the small rnd/scope set
// L2-resident (normal loads/stores). All loads front-batched for MLP.
__global__ void __launch_bounds__(256) k_step(
        const float* __restrict__ rnd, const float* __restrict__ lsig_p,
        float* __restrict__ out, int k) {
    __shared__ unsigned long long sred[8];
    int tid = threadIdx.x;
    int b   = blockIdx.x >> 6;
    int pin = (blockIdx.x & 63) * 1024 + tid;

    unsigned long long sl = g_slots[k][b];
    unsigned int idx = 0xFFFFFFFFu - (unsigned int)(sl & 0xFFFFFFFFull);
    size_t seedbase = (size_t)b * HW + idx;
    float4 s0 = __ldg(&g_feat0[seedbase]);
    float4 s1 = __ldg(&g_feat1[seedbase]);
    float neg_inv_sigma = -1.0f / __expf(__ldg(lsig_p));

    float* masks  = out;
    float* scopes = out + (size_t)BATCH * KSTEPS * HW;
    const float* scope_in = scopes + ((size_t)b * KSTEPS + k)     * HW;
    float* scope_out = scopes + ((size_t)b * KSTEPS + k + 1) * HW;
    float* mask_out  = masks  + ((size_t)b * KSTEPS + k)     * HW;
    float* mask_last = masks  + ((size_t)b * KSTEPS + KSTEPS - 1) * HW;

    // ---- front-batched loads (16 LDG issued back-to-back) ----
    float  sj[4], rj[4];
    float4 f0v[4], f1v[4];
    #pragma unroll
    for (int j = 0; j < 4; j++) {
        int p = pin + 256 * j;
        size_t base = (size_t)b * HW + p;
        sj[j]  = scope_in[p];                 // L2-resident (written last step)
        rj[j]  = rnd[base];                   // L2-resident (8 MB, protected)
        f0v[j] = __ldcs(&g_feat0[base]);      // streamed, evict-first
        f1v[j] = __ldcs(&g_feat1[base]);      // streamed, evict-first
    }

    // ---- compute + store ----
    unsigned long long best = 0ull;
    #pragma unroll
    for (int j = 0; j < 4; j++) {
        int p = pin + 256 * j;
        float4 f0 = f0v[j], f1 = f1v[j];
        float d = 0.0f, t;
        t = f0.x - s0.x; d = fmaf(t, t, d);
        t = f0.y - s0.y; d = fmaf(t, t, d);
        t = f0.z - s0.z; d = fmaf(t, t, d);
        t = f0.w - s0.w; d = fmaf(t, t, d);
        t = f1.x - s1.x; d = fmaf(t, t, d);
        t = f1.y - s1.y; d = fmaf(t, t, d);
        t = f1.z - s1.z; d = fmaf(t, t, d);
        t = f1.w - s1.w; d = fmaf(t, t, d);
        float a = __expf(d * neg_inv_sigma);
        a = fminf(fmaxf(a, 0.01f), 0.99f);
        float s  = sj[j];
        float m  = s * a;
        float ns = s * (1.0f - a);
        __stwt(&mask_out[p], m);            // never re-read: write-through
        scope_out[p] = ns;                  // re-read next step: keep in L2
        if (k == KSTEPS - 2) {
            __stwt(&mask_last[p], ns);      // masks[:,10] = final scope
        } else {
            unsigned long long pk = pack_key(rj[j] * ns, p);
            if (pk > best) best = pk;
        }
    }

    if (k != KSTEPS - 2) {
        best = block_reduce_max(best, sred);
        if (tid == 0) atomicMax(&g_slots[k + 1][b], best);
    }
}

// -------------------------------------------------------------------------
extern "C" void kernel_launch(void* const* d_in, const int* in_sizes, int n_in,
                              void* d_out, int out_size) {
    const float* x    = (const float*)d_in[0];
    const float* rnd  = (const float*)d_in[1];
    const float* w    = (const float*)d_in[2];
    const float* bias = (const float*)d_in[3];
    const float* gate = (const float*)d_in[4];
    const float* lsig = (const float*)d_in[5];
    float* out = (float*)d_out;

    k_init_slots<<<1, KSTEPS * BATCH>>>();
    k_feat<<<BATCH * 64, 256>>>(x, rnd, w, bias, gate, out);
    for (int k = 0; k < KSTEPS - 1; k++)
        k_step<<<BATCH * 64, 256>>>(rnd, lsig, out, k);
}

// round 6
// speedup vs baseline: 1.0399x; 1.0399x over previous
#include <cuda_runtime.h>
#include <cstdint>

#define BATCH  32
#define CIN    64
#define COUT   8
#define HW     65536
#define KSTEPS 11

// Scratch (static __device__ — allocation-free per harness rules)
__device__ float4 g_feat0[(size_t)BATCH * HW];           // 32 MB: channels 0-3
__device__ float4 g_feat1[(size_t)BATCH * HW];           // 32 MB: channels 4-7
__device__ unsigned long long g_slots[KSTEPS][BATCH];    // argmax slots per step

// -------------------------------------------------------------------------
__global__ void k_init_slots() {
    int t = threadIdx.x;
    if (t < KSTEPS * BATCH) ((unsigned long long*)g_slots)[t] = 0ull;
}

// Block-wide max of packed (value_bits<<32 | ~idx). Valid on thread 0.
__device__ __forceinline__ unsigned long long block_reduce_max(
        unsigned long long v, unsigned long long* sred) {
    #pragma unroll
    for (int s = 16; s > 0; s >>= 1) {
        unsigned long long o = __shfl_down_sync(0xFFFFFFFFu, v, s);
        if (o > v) v = o;
    }
    if ((threadIdx.x & 31) == 0) sred[threadIdx.x >> 5] = v;
    __syncthreads();
    if (threadIdx.x < 8) {
        v = sred[threadIdx.x];
        #pragma unroll
        for (int s = 4; s > 0; s >>= 1) {
            unsigned long long o = __shfl_down_sync(0x000000FFu, v, s);
            if (o > v) v = o;
        }
    }
    return v;
}

__device__ __forceinline__ unsigned long long pack_key(float key, int idx) {
    return ((unsigned long long)__float_as_uint(key) << 32)
         | (unsigned long long)(0xFFFFFFFFu - (unsigned)idx);
}

// Packed fp32x2 helpers (sm_103a packed-FMA pipe, rt=1 vs 2 for scalar FFMA)
__device__ __forceinline__ unsigned long long pack2(float lo, float hi) {
    unsigned long long r;
    asm("mov.b64 %0, {%1, %2};" : "=l"(r) : "f"(lo), "f"(hi));
    return r;
}
__device__ __forceinline__ void unpack2(float& lo, float& hi, unsigned long long v) {
    asm("mov.b64 {%0, %1}, %2;" : "=f"(lo), "=f"(hi) : "l"(v));
}
__device__ __forceinline__ void ffma2(unsigned long long& d,
                                      unsigned long long a, unsigned long long b) {
    asm("fma.rn.f32x2 %0, %1, %2, %0;" : "+l"(d) : "l"(a), "l"(b));
}
__device__ __forceinline__ unsigned long long fadd2(unsigned long long a,
                                                    unsigned long long b) {
    unsigned long long r;
    asm("add.rn.f32x2 %0, %1, %2;" : "=l"(r) : "l"(a), "l"(b));
    return r;
}

// -------------------------------------------------------------------------
// Kernel 0: feat = gate*(W@x + b) + coord grid; scopes[:,0]=1;
// partial argmax of rand into slot 0. Inner GEMM uses packed f32x2 FMA.
// Grid: 2048 blocks x 256 threads, 4 consecutive pixels/thread (x coalesced).
__global__ void __launch_bounds__(256) k_feat(
        const float* __restrict__ x, const float* __restrict__ rnd,
        const float* __restrict__ w, const float* __restrict__ bias,
        const float* __restrict__ gate_p, float* __restrict__ out) {
    __shared__ unsigned long long swp[CIN * COUT];   // duplicated packed weights [c][o]
    __shared__ float sb[COUT];
    __shared__ unsigned long long sred[8];
    int tid = threadIdx.x;
    for (int i = tid; i < CIN * COUT; i += 256) {
        int o = i / CIN, c = i % CIN;
        float wv = w[i];
        swp[c * COUT + o] = pack2(wv, wv);           // transposed + duplicated
    }
    if (tid < COUT) sb[tid] = bias[tid];
    __syncthreads();

    float gate = *gate_p;
    int b     = blockIdx.x >> 6;
    int pin   = (blockIdx.x & 63) * 1024 + tid * 4;   // pixel-in-batch
    const float4* x4 = (const float4*)x + ((size_t)b * CIN) * (HW / 4) + (pin >> 2);

    unsigned long long acc[COUT][2];                  // pairs: px{0,1}, px{2,3}
    #pragma unroll
    for (int o = 0; o < COUT; o++) {
        float bv = sb[o];
        acc[o][0] = pack2(bv, bv);
        acc[o][1] = pack2(bv, bv);
    }

    #pragma unroll 8
    for (int c = 0; c < CIN; c++) {
        float4 v = __ldcs(&x4[(size_t)c * (HW / 4)]);   // x never re-read: stream
        unsigned long long xp0 = pack2(v.x, v.y);
        unsigned long long xp1 = pack2(v.z, v.w);
        #pragma unroll
        for (int o = 0; o < COUT; o++) {
            unsigned long long wp = swp[c * COUT + o];
            ffma2(acc[o][0], wp, xp0);
            ffma2(acc[o][1], wp, xp1);
        }
    }

    float accf[COUT][4];
    #pragma unroll
    for (int o = 0; o < COUT; o++) {
        unpack2(accf[o][0], accf[o][1], acc[o][0]);
        unpack2(accf[o][2], accf[o][3], acc[o][1]);
    }

    const float step = 2.0f / 255.0f;
    #pragma unroll
    for (int j = 0; j < 4; j++) {
        int p  = pin + j;
        int h  = p >> 8;
        int wi = p & 255;
        float4 f0, f1;
        f0.x = gate * accf[0][j]; f0.y = gate * accf[1][j];
        f0.z = gate * accf[2][j]; f0.w = gate * accf[3][j];
        f1.x = gate * accf[4][j]; f1.y = gate * accf[5][j];
        f1.z = fmaf((float)h,  step, -1.0f) + gate * accf[6][j];
        f1.w = fmaf((float)wi, step, -1.0f) + gate * accf[7][j];
        size_t fb = (size_t)b * HW + p;
        g_feat0[fb] = f0;                    // normal store: drain lazily from L2
        g_feat1[fb] = f1;
    }

    // scopes[b,0,:] = 1  (re-read by step 0 -> normal store, stays in L2)
    float4 ones = make_float4(1.0f, 1.0f, 1.0f, 1.0f);
    float* scopes = out + (size_t)BATCH * KSTEPS * HW;
    *(float4*)&scopes[((size_t)b * KSTEPS) * HW + pin] = ones;

    // argmax of rand (scope == 1) for step 0
    float4 rv = ((const float4*)rnd)[((size_t)b * HW + pin) >> 2];
    float rj[4] = {rv.x, rv.y, rv.z, rv.w};
    unsigned long long best = 0ull;
    #pragma unroll
    for (int j = 0; j < 4; j++) {
        unsigned long long pk = pack_key(rj[j], pin + j);
        if (pk > best) best = pk;
    }
    best = block_reduce_max(best, sred);
    if (tid == 0) atomicMax(&g_slots[0][b], best);
}

// -------------------------------------------------------------------------
// Step kernel k = 0..9: seed from slot[k]; alpha; write masks[:,k],
// scopes[:,k+1]; partial argmax into slot[k+1] (k==9 -> masks[:,10]=scope).
// Policy: STREAM the big feat set (__ldcs), keep the small rnd/scope set
// L2-resident. All loads front-batched; distance in packed f32x2.
__global__ void __launch_bounds__(256) k_step(
        const float* __restrict__ rnd, const float* __restrict__ lsig_p,
        float* __restrict__ out, int k) {
    __shared__ unsigned long long sred[8];
    int tid = threadIdx.x;
    int b   = blockIdx.x >> 6;
    int pin = (blockIdx.x & 63) * 1024 + tid;
    bool last = (k == KSTEPS - 2);

    unsigned long long sl = g_slots[k][b];
    unsigned int idx = 0xFFFFFFFFu - (unsigned int)(sl & 0xFFFFFFFFull);
    size_t seedbase = (size_t)b * HW + idx;
    float4 s0 = __ldg(&g_feat0[seedbase]);
    float4 s1 = __ldg(&g_feat1[seedbase]);
    // negated seed pairs for packed (f - s) via add
    unsigned long long ns01 = pack2(-s0.x, -s0.y);
    unsigned long long ns23 = pack2(-s0.z, -s0.w);
    unsigned long long ns45 = pack2(-s1.x, -s1.y);
    unsigned long long ns67 = pack2(-s1.z, -s1.w);
    float neg_inv_sigma = -1.0f / __expf(__ldg(lsig_p));

    float* masks  = out;
    float* scopes = out + (size_t)BATCH * KSTEPS * HW;
    const float* scope_in = scopes + ((size_t)b * KSTEPS + k)     * HW;
    float* scope_out = scopes + ((size_t)b * KSTEPS + k + 1) * HW;
    float* mask_out  = masks  + ((size_t)b * KSTEPS + k)     * HW;
    float* mask_last = masks  + ((size_t)b * KSTEPS + KSTEPS - 1) * HW;

    // ---- front-batched loads ----
    float  sj[4], rj[4];
    float4 f0v[4], f1v[4];
    #pragma unroll
    for (int j = 0; j < 4; j++) {
        int p = pin + 256 * j;
        size_t base = (size_t)b * HW + p;
        sj[j]  = scope_in[p];                 // L2-resident (written last step)
        if (!last) rj[j] = rnd[base];         // L2-resident (8 MB, protected)
        f0v[j] = __ldcs(&g_feat0[base]);      // streamed, evict-first
        f1v[j] = __ldcs(&g_feat1[base]);      // streamed, evict-first
    }

    // ---- compute + store ----
    unsigned long long best = 0ull;
    #pragma unroll
    for (int j = 0; j < 4; j++) {
        int p = pin + 256 * j;
        float4 f0 = f0v[j], f1 = f1v[j];
        // packed squared distance: d2 accumulates (even, odd) channel pairs
        unsigned long long d2 = pack2(0.0f, 0.0f);
        unsigned long long t2;
        t2 = fadd2(pack2(f0.x, f0.y), ns01); ffma2(d2, t2, t2);
        t2 = fadd2(pack2(f0.z, f0.w), ns23); ffma2(d2, t2, t2);
        t2 = fadd2(pack2(f1.x, f1.y), ns45); ffma2(d2, t2, t2);
        t2 = fadd2(pack2(f1.z, f1.w), ns67); ffma2(d2, t2, t2);
        float de, dodd; unpack2(de, dodd, d2);
        float d = de + dodd;
        float a = __expf(d * neg_inv_sigma);
        a = fminf(fmaxf(a, 0.01f), 0.99f);
        float s  = sj[j];
        float m  = s * a;
        float ns = s * (1.0f - a);
        __stwt(&mask_out[p], m);            // never re-read: write-through
        if (last) {
            __stwt(&scope_out[p], ns);      // final scopes slice: never re-read
            __stwt(&mask_last[p], ns);      // masks[:,10] = final scope
        } else {
            scope_out[p] = ns;              // re-read next step: keep in L2
            unsigned long long pk = pack_key(rj[j] * ns, p);
            if (pk > best) best = pk;
        }
    }

    if (!last) {
        best = block_reduce_max(best, sred);
        if (tid == 0) atomicMax(&g_slots[k + 1][b], best);
    }
}

// -------------------------------------------------------------------------
extern "C" void kernel_launch(void* const* d_in, const int* in_sizes, int n_in,
                              void* d_out, int out_size) {
    const float* x    = (const float*)d_in[0];
    const float* rnd  = (const float*)d_in[1];
    const float* w    = (const float*)d_in[2];
    const float* bias = (const float*)d_in[3];
    const float* gate = (const float*)d_in[4];
    const float* lsig = (const float*)d_in[5];
    float* out = (float*)d_out;

    k_init_slots<<<1, KSTEPS * BATCH>>>();
    k_feat<<<BATCH * 64, 256>>>(x, rnd, w, bias, gate, out);
    for (int k = 0; k < KSTEPS - 1; k++)
        k_step<<<BATCH * 64, 256>>>(rnd, lsig, out, k);
}

// round 7
// speedup vs baseline: 1.1604x; 1.1159x over previous
#include <cuda_runtime.h>
#include <cstdint>

#define BATCH  32
#define CIN    64
#define COUT   8
#define HW     65536
#define KSTEPS 11

// Scratch (static __device__ — allocation-free per harness rules)
__device__ float4 g_feat0[(size_t)BATCH * HW];           // 32 MB: channels 0-3
__device__ float4 g_feat1[(size_t)BATCH * HW];           // 32 MB: channels 4-7
__device__ unsigned long long g_slots[KSTEPS][BATCH];    // argmax slots per step

// -------------------------------------------------------------------------
__global__ void k_init_slots() {
    int t = threadIdx.x;
    if (t < KSTEPS * BATCH) ((unsigned long long*)g_slots)[t] = 0ull;
}

// Block-wide max of packed (value_bits<<32 | ~idx). Valid on thread 0.
__device__ __forceinline__ unsigned long long block_reduce_max(
        unsigned long long v, unsigned long long* sred) {
    #pragma unroll
    for (int s = 16; s > 0; s >>= 1) {
        unsigned long long o = __shfl_down_sync(0xFFFFFFFFu, v, s);
        if (o > v) v = o;
    }
    if ((threadIdx.x & 31) == 0) sred[threadIdx.x >> 5] = v;
    __syncthreads();
    if (threadIdx.x < 8) {
        v = sred[threadIdx.x];
        #pragma unroll
        for (int s = 4; s > 0; s >>= 1) {
            unsigned long long o = __shfl_down_sync(0x000000FFu, v, s);
            if (o > v) v = o;
        }
    }
    return v;
}

__device__ __forceinline__ unsigned long long pack_key(float key, int idx) {
    return ((unsigned long long)__float_as_uint(key) << 32)
         | (unsigned long long)(0xFFFFFFFFu - (unsigned)idx);
}

// Packed fp32x2 helpers (sm_103a packed-FMA pipe) — used in k_feat GEMM
__device__ __forceinline__ unsigned long long pack2(float lo, float hi) {
    unsigned long long r;
    asm("mov.b64 %0, {%1, %2};" : "=l"(r) : "f"(lo), "f"(hi));
    return r;
}
__device__ __forceinline__ void unpack2(float& lo, float& hi, unsigned long long v) {
    asm("mov.b64 {%0, %1}, %2;" : "=f"(lo), "=f"(hi) : "l"(v));
}
__device__ __forceinline__ void ffma2(unsigned long long& d,
                                      unsigned long long a, unsigned long long b) {
    asm("fma.rn.f32x2 %0, %1, %2, %0;" : "+l"(d) : "l"(a), "l"(b));
}

// ---- mbarrier / bulk-async helpers -------------------------------------
__device__ __forceinline__ uint32_t smem_u32(const void* p) {
    return (uint32_t)__cvta_generic_to_shared(p);
}
__device__ __forceinline__ void mbar_init(uint32_t mbar, uint32_t count) {
    asm volatile("mbarrier.init.shared.b64 [%0], %1;" :: "r"(mbar), "r"(count) : "memory");
}
__device__ __forceinline__ void mbar_expect_tx(uint32_t mbar, uint32_t bytes) {
    asm volatile("mbarrier.arrive.expect_tx.shared.b64 _, [%0], %1;"
                 :: "r"(mbar), "r"(bytes) : "memory");
}
__device__ __forceinline__ void mbar_wait(uint32_t mbar, uint32_t parity) {
    asm volatile(
        "{\n\t"
        ".reg .pred P;\n\t"
        "WAIT_%=:\n\t"
        "mbarrier.try_wait.parity.shared::cta.b64 P, [%0], %1;\n\t"
        "@P bra DONE_%=;\n\t"
        "bra WAIT_%=;\n\t"
        "DONE_%=:\n\t"
        "}"
        :: "r"(mbar), "r"(parity) : "memory");
}
__device__ __forceinline__ void bulk_g2s(uint32_t dst_smem, const void* src_gmem,
                                         uint32_t bytes, uint32_t mbar) {
    asm volatile(
        "cp.async.bulk.shared::cta.global.mbarrier::complete_tx::bytes "
        "[%0], [%1], %2, [%3];"
        :: "r"(dst_smem), "l"(src_gmem), "r"(bytes), "r"(mbar) : "memory");
}

// -------------------------------------------------------------------------
// Kernel 0: feat = gate*(W@x + b) + coord grid; scopes[:,0]=1;
// partial argmax of rand into slot 0. Inner GEMM uses packed f32x2 FMA.
__global__ void __launch_bounds__(256) k_feat(
        const float* __restrict__ x, const float* __restrict__ rnd,
        const float* __restrict__ w, const float* __restrict__ bias,
        const float* __restrict__ gate_p, float* __restrict__ out) {
    __shared__ unsigned long long swp[CIN * COUT];   // duplicated packed weights [c][o]
    __shared__ float sb[COUT];
    __shared__ unsigned long long sred[8];
    int tid = threadIdx.x;
    for (int i = tid; i < CIN * COUT; i += 256) {
        int o = i / CIN, c = i % CIN;
        float wv = w[i];
        swp[c * COUT + o] = pack2(wv, wv);           // transposed + duplicated
    }
    if (tid < COUT) sb[tid] = bias[tid];
    __syncthreads();

    float gate = *gate_p;
    int b     = blockIdx.x >> 6;
    int pin   = (blockIdx.x & 63) * 1024 + tid * 4;   // pixel-in-batch
    const float4* x4 = (const float4*)x + ((size_t)b * CIN) * (HW / 4) + (pin >> 2);

    unsigned long long acc[COUT][2];                  // pairs: px{0,1}, px{2,3}
    #pragma unroll
    for (int o = 0; o < COUT; o++) {
        float bv = sb[o];
        acc[o][0] = pack2(bv, bv);
        acc[o][1] = pack2(bv, bv);
    }

    #pragma unroll 8
    for (int c = 0; c < CIN; c++) {
        float4 v = __ldcs(&x4[(size_t)c * (HW / 4)]);   // x never re-read: stream
        unsigned long long xp0 = pack2(v.x, v.y);
        unsigned long long xp1 = pack2(v.z, v.w);
        #pragma unroll
        for (int o = 0; o < COUT; o++) {
            unsigned long long wp = swp[c * COUT + o];
            ffma2(acc[o][0], wp, xp0);
            ffma2(acc[o][1], wp, xp1);
        }
    }

    float accf[COUT][4];
    #pragma unroll
    for (int o = 0; o < COUT; o++) {
        unpack2(accf[o][0], accf[o][1], acc[o][0]);
        unpack2(accf[o][2], accf[o][3], acc[o][1]);
    }

    const float step = 2.0f / 255.0f;
    #pragma unroll
    for (int j = 0; j < 4; j++) {
        int p  = pin + j;
        int h  = p >> 8;
        int wi = p & 255;
        float4 f0, f1;
        f0.x = gate * accf[0][j]; f0.y = gate * accf[1][j];
        f0.z = gate * accf[2][j]; f0.w = gate * accf[3][j];
        f1.x = gate * accf[4][j]; f1.y = gate * accf[5][j];
        f1.z = fmaf((float)h,  step, -1.0f) + gate * accf[6][j];
        f1.w = fmaf((float)wi, step, -1.0f) + gate * accf[7][j];
        size_t fb = (size_t)b * HW + p;
        g_feat0[fb] = f0;                    // normal store: drain lazily from L2
        g_feat1[fb] = f1;
    }

    // scopes[b,0,:] = 1  (re-read by step 0)
    float4 ones = make_float4(1.0f, 1.0f, 1.0f, 1.0f);
    float* scopes = out + (size_t)BATCH * KSTEPS * HW;
    *(float4*)&scopes[((size_t)b * KSTEPS) * HW + pin] = ones;

    // argmax of rand (scope == 1) for step 0
    float4 rv = ((const float4*)rnd)[((size_t)b * HW + pin) >> 2];
    float rj[4] = {rv.x, rv.y, rv.z, rv.w};
    unsigned long long best = 0ull;
    #pragma unroll
    for (int j = 0; j < 4; j++) {
        unsigned long long pk = pack_key(rj[j], pin + j);
        if (pk > best) best = pk;
    }
    best = block_reduce_max(best, sred);
    if (tid == 0) atomicMax(&g_slots[0][b], best);
}

// -------------------------------------------------------------------------
// Step kernel k = 0..9: bulk-async stage feat0/feat1/scope/rnd (40 KB) into
// smem via cp.async.bulk + mbarrier, compute alpha from smem, write
// masks[:,k], scopes[:,k+1], partial argmax into slot[k+1]
// (k==9 -> masks[:,10] = final scope, no rnd/argmax).
__global__ void __launch_bounds__(256) k_step(
        const float* __restrict__ rnd, const float* __restrict__ lsig_p,
        float* __restrict__ out, int k) {
    __shared__ __align__(16) float4 s_f0[1024];      // 16 KB
    __shared__ __align__(16) float4 s_f1[1024];      // 16 KB
    __shared__ __align__(16) float  s_sc[1024];      //  4 KB
    __shared__ __align__(16) float  s_rn[1024];      //  4 KB
    __shared__ unsigned long long sred[8];
    __shared__ __align__(8) unsigned long long s_mbar;

    int tid  = threadIdx.x;
    int b    = blockIdx.x >> 6;
    int pin0 = (blockIdx.x & 63) * 1024;             // block's first pixel
    bool last = (k == KSTEPS - 2);
    size_t gbase = (size_t)b * HW + pin0;

    float* masks  = out;
    float* scopes = out + (size_t)BATCH * KSTEPS * HW;
    const float* scope_in = scopes + ((size_t)b * KSTEPS + k)     * HW;
    float* scope_out = scopes + ((size_t)b * KSTEPS + k + 1) * HW;
    float* mask_out  = masks  + ((size_t)b * KSTEPS + k)     * HW;
    float* mask_last = masks  + ((size_t)b * KSTEPS + KSTEPS - 1) * HW;

    uint32_t mbar = smem_u32(&s_mbar);
    if (tid == 0) mbar_init(mbar, 1);
    __syncthreads();
    if (tid == 0) {
        uint32_t bytes = 16384 + 16384 + 4096 + (last ? 0u : 4096u);
        mbar_expect_tx(mbar, bytes);
        bulk_g2s(smem_u32(s_f0), &g_feat0[gbase], 16384, mbar);
        bulk_g2s(smem_u32(s_f1), &g_feat1[gbase], 16384, mbar);
        bulk_g2s(smem_u32(s_sc), &scope_in[pin0],  4096, mbar);
        if (!last) bulk_g2s(smem_u32(s_rn), &rnd[gbase], 4096, mbar);
    }

    // Overlap: seed + constants while bulk copies are in flight
    unsigned long long sl = g_slots[k][b];
    unsigned int idx = 0xFFFFFFFFu - (unsigned int)(sl & 0xFFFFFFFFull);
    size_t seedbase = (size_t)b * HW + idx;
    float4 s0 = __ldg(&g_feat0[seedbase]);
    float4 s1 = __ldg(&g_feat1[seedbase]);
    float neg_inv_sigma = -1.0f / __expf(__ldg(lsig_p));

    mbar_wait(mbar, 0);

    unsigned long long best = 0ull;
    #pragma unroll
    for (int j = 0; j < 4; j++) {
        int pl = tid + 256 * j;                      // pixel within block
        int p  = pin0 + pl;
        float4 f0 = s_f0[pl];
        float4 f1 = s_f1[pl];
        float d = 0.0f, t;
        t = f0.x - s0.x; d = fmaf(t, t, d);
        t = f0.y - s0.y; d = fmaf(t, t, d);
        t = f0.z - s0.z; d = fmaf(t, t, d);
        t = f0.w - s0.w; d = fmaf(t, t, d);
        t = f1.x - s1.x; d = fmaf(t, t, d);
        t = f1.y - s1.y; d = fmaf(t, t, d);
        t = f1.z - s1.z; d = fmaf(t, t, d);
        t = f1.w - s1.w; d = fmaf(t, t, d);
        float a = __expf(d * neg_inv_sigma);
        a = fminf(fmaxf(a, 0.01f), 0.99f);
        float s  = s_sc[pl];
        float m  = s * a;
        float ns = s * (1.0f - a);
        __stwt(&mask_out[p], m);            // never re-read: write-through
        if (last) {
            __stwt(&scope_out[p], ns);      // final scopes slice: never re-read
            __stwt(&mask_last[p], ns);      // masks[:,10] = final scope
        } else {
            scope_out[p] = ns;              // re-read next step: keep in L2
            unsigned long long pk = pack_key(s_rn[pl] * ns, p);
            if (pk > best) best = pk;
        }
    }

    if (!last) {
        best = block_reduce_max(best, sred);
        if (tid == 0) atomicMax(&g_slots[k + 1][b], best);
    }
}

// -------------------------------------------------------------------------
extern "C" void kernel_launch(void* const* d_in, const int* in_sizes, int n_in,
                              void* d_out, int out_size) {
    const float* x    = (const float*)d_in[0];
    const float* rnd  = (const float*)d_in[1];
    const float* w    = (const float*)d_in[2];
    const float* bias = (const float*)d_in[3];
    const float* gate = (const float*)d_in[4];
    const float* lsig = (const float*)d_in[5];
    float* out = (float*)d_out;

    k_init_slots<<<1, KSTEPS * BATCH>>>();
    k_feat<<<BATCH * 64, 256>>>(x, rnd, w, bias, gate, out);
    for (int k = 0; k < KSTEPS - 1; k++)
        k_step<<<BATCH * 64, 256>>>(rnd, lsig, out, k);
}